// round 1
// baseline (speedup 1.0000x reference)
#include <cuda_runtime.h>
#include <cuda_bf16.h>
#include <math.h>

// Problem constants
#define B_SZ   4096
#define D_SZ   512
#define K_SZ   256
#define N_SZ   8

// Bilinear tile config
#define BT 128   // batch rows per CTA
#define JT 128   // j-columns per tile
#define CK 16    // i-reduction chunk

// ---------------------------------------------------------------------------
// Scratch (device globals; no allocations allowed)
// ---------------------------------------------------------------------------
__device__ __align__(16) float g_S[B_SZ * D_SZ];   // subj phrase embed
__device__ __align__(16) float g_V[B_SZ * D_SZ];   // verb
__device__ __align__(16) float g_O[B_SZ * D_SZ];   // obj
__device__ __align__(16) float g_L[B_SZ * K_SZ];   // linear-term buffer (reused 3x)
__device__ __align__(16) float g_R1[B_SZ * K_SZ];
__device__ __align__(16) float g_R2[B_SZ * K_SZ];

// ---------------------------------------------------------------------------
// Packed f32x2 helpers (Blackwell FFMA2 — only reachable via PTX)
// ---------------------------------------------------------------------------
__device__ __forceinline__ void ffma2(unsigned long long& d,
                                      const unsigned long long a,
                                      const unsigned long long b) {
    asm("fma.rn.f32x2 %0, %1, %2, %0;" : "+l"(d) : "l"(a), "l"(b));
}

__device__ __forceinline__ unsigned long long splat2(float x) {
    unsigned long long r;
    unsigned int u = __float_as_uint(x);
    asm("mov.b64 %0, {%1, %1};" : "=l"(r) : "r"(u));
    return r;
}

// ---------------------------------------------------------------------------
// Kernel 1: phrase embedding  out[b,:] = sum_n w[b,n] * emb[ids[b,n],:]
// grid = B, block = 128 (one float4 per thread over D=512)
// ---------------------------------------------------------------------------
__global__ void embed_kernel(const int* __restrict__ ids,
                             const float* __restrict__ w,
                             const float* __restrict__ emb,
                             float* __restrict__ out) {
    int b = blockIdx.x;
    int t = threadIdx.x;  // 0..127
    const float4* emb4 = (const float4*)emb;
    float4 acc = make_float4(0.f, 0.f, 0.f, 0.f);
#pragma unroll
    for (int n = 0; n < N_SZ; n++) {
        int   id = __ldg(&ids[b * N_SZ + n]);
        float wn = __ldg(&w[b * N_SZ + n]);
        float4 e = __ldg(&emb4[(size_t)id * (D_SZ / 4) + t]);
        acc.x = fmaf(wn, e.x, acc.x);
        acc.y = fmaf(wn, e.y, acc.y);
        acc.z = fmaf(wn, e.z, acc.z);
        acc.w = fmaf(wn, e.w, acc.w);
    }
    ((float4*)out)[(size_t)b * (D_SZ / 4) + t] = acc;
}

// ---------------------------------------------------------------------------
// Kernel 2: linear term  L[b,k] = bias[k] + sum_d X1[b,d]W[k,d] + X2[b,d]W[k,D1+d]
// grid = (B/16, K/16), block = 256; each thread one output.
// ---------------------------------------------------------------------------
__global__ __launch_bounds__(256)
void linear_kernel(const float* __restrict__ X1, const float* __restrict__ X2,
                   const float* __restrict__ W, const float* __restrict__ bias,
                   float* __restrict__ L, int D1) {
    __shared__ float Xs[16][68];
    __shared__ float Ws[16][68];
    int tid = threadIdx.x;
    int tb = tid >> 4, tk = tid & 15;
    int b0 = blockIdx.x * 16, k0 = blockIdx.y * 16;
    int lr = tid >> 4;
    int lc = (tid & 15) * 4;
    float acc = 0.f;
#pragma unroll
    for (int h = 0; h < 2; h++) {
        const float* X = h ? X2 : X1;
        int woff = h * D1;
        for (int dc = 0; dc < D1; dc += 64) {
            __syncthreads();
            *(float4*)&Xs[lr][lc] =
                *(const float4*)&X[(size_t)(b0 + lr) * D1 + dc + lc];
            *(float4*)&Ws[lr][lc] =
                *(const float4*)&W[(size_t)(k0 + lr) * (2 * D1) + woff + dc + lc];
            __syncthreads();
#pragma unroll
            for (int d = 0; d < 64; d++)
                acc = fmaf(Xs[tb][d], Ws[tk][d], acc);
        }
    }
    L[(size_t)(b0 + tb) * K_SZ + (k0 + tk)] = acc + __ldg(&bias[k0 + tk]);
}

// ---------------------------------------------------------------------------
// Kernel 3: fused bilinear + linear + tanh
//   OUT[b,k] = tanh( sum_{i,j} X1[b,i] * T[k,i,j] * X2[b,j]  +  L[b,k] )
// grid = (B/BT, K). Per CTA: GEMM tile (128 b x 128 j) over i, epilogue
// weights by X2[b,j] and reduces over j. Inner loop uses packed FFMA2.
// ---------------------------------------------------------------------------
__global__ __launch_bounds__(256, 2)
void bilinear_kernel(const float* __restrict__ T, const float* __restrict__ X1,
                     const float* __restrict__ X2, const float* __restrict__ L,
                     float* __restrict__ OUT, int Di, int Dj) {
    __shared__ __align__(16) float As[CK][BT + 4];  // X1 chunk, transposed [i][b]
    __shared__ __align__(16) float Bs[CK][JT];      // T chunk [i][j]

    int tid = threadIdx.x;
    int tx = tid & 15, ty = tid >> 4;
    int k = blockIdx.y;
    int b0 = blockIdx.x * BT;
    const float* Tk = T + (size_t)k * Di * Dj;

    float yacc[8];
#pragma unroll
    for (int i = 0; i < 8; i++) yacc[i] = 0.f;

    for (int jt = 0; jt < Dj; jt += JT) {
        unsigned long long c2[8][4];  // 8 b-rows x 8 j-cols (packed f32x2)
#pragma unroll
        for (int i = 0; i < 8; i++)
#pragma unroll
            for (int j = 0; j < 4; j++) c2[i][j] = 0ull;

        for (int ic = 0; ic < Di; ic += CK) {
            __syncthreads();
#pragma unroll
            for (int l = 0; l < 8; l++) {  // load X1 chunk (2048 elems)
                int idx = tid + l * 256;
                int bb = idx >> 4, ii = idx & 15;
                As[ii][bb] = X1[(size_t)(b0 + bb) * Di + ic + ii];
            }
#pragma unroll
            for (int l = 0; l < 8; l++) {  // load T chunk (2048 elems)
                int idx = tid + l * 256;
                int rr = idx >> 7, cc = idx & 127;
                Bs[rr][cc] = Tk[(size_t)(ic + rr) * Dj + jt + cc];
            }
            __syncthreads();
#pragma unroll
            for (int kk = 0; kk < CK; kk++) {
                ulonglong2 bp0 = *(const ulonglong2*)&Bs[kk][tx * 8];
                ulonglong2 bp1 = *(const ulonglong2*)&Bs[kk][tx * 8 + 4];
                unsigned long long bv0 = bp0.x, bv1 = bp0.y;
                unsigned long long bv2 = bp1.x, bv3 = bp1.y;
#pragma unroll
                for (int i = 0; i < 8; i++) {
                    unsigned long long a2 = splat2(As[kk][ty * 8 + i]);
                    ffma2(c2[i][0], a2, bv0);
                    ffma2(c2[i][1], a2, bv1);
                    ffma2(c2[i][2], a2, bv2);
                    ffma2(c2[i][3], a2, bv3);
                }
            }
        }
        // epilogue: yacc[b] += sum_j C[b,j] * X2[b,j]
#pragma unroll
        for (int i = 0; i < 8; i++) {
            const float* vrow =
                &X2[(size_t)(b0 + ty * 8 + i) * Dj + jt + tx * 8];
            float4 v0 = __ldg((const float4*)vrow);
            float4 v1 = __ldg((const float4*)(vrow + 4));
            float vv[8] = {v0.x, v0.y, v0.z, v0.w, v1.x, v1.y, v1.z, v1.w};
#pragma unroll
            for (int jp = 0; jp < 4; jp++) {
                float lo = __uint_as_float((unsigned int)(c2[i][jp]));
                float hi = __uint_as_float((unsigned int)(c2[i][jp] >> 32));
                yacc[i] = fmaf(lo, vv[2 * jp], yacc[i]);
                yacc[i] = fmaf(hi, vv[2 * jp + 1], yacc[i]);
            }
        }
    }

    // reduce over tx (16 lanes per b-row group)
#pragma unroll
    for (int off = 8; off >= 1; off >>= 1)
#pragma unroll
        for (int i = 0; i < 8; i++)
            yacc[i] += __shfl_xor_sync(0xffffffffu, yacc[i], off, 16);

    if (tx == 0) {
#pragma unroll
        for (int i = 0; i < 8; i++) {
            size_t b = (size_t)b0 + ty * 8 + i;
            OUT[b * K_SZ + k] = tanhf(yacc[i] + L[b * K_SZ + k]);
        }
    }
}

// ---------------------------------------------------------------------------
// Launch
// ---------------------------------------------------------------------------
extern "C" void kernel_launch(void* const* d_in, const int* in_sizes, int n_in,
                              void* d_out, int out_size) {
    const int*   subj_id = (const int*)d_in[0];
    const float* subj_w  = (const float*)d_in[1];
    const int*   verb_id = (const int*)d_in[2];
    const float* verb_w  = (const float*)d_in[3];
    const int*   obj_id  = (const int*)d_in[4];
    const float* obj_w   = (const float*)d_in[5];
    const float* emb     = (const float*)d_in[6];
    const float* t1      = (const float*)d_in[7];
    const float* t2      = (const float*)d_in[8];
    const float* t3      = (const float*)d_in[9];
    const float* W1      = (const float*)d_in[10];
    const float* b1      = (const float*)d_in[11];
    const float* W2      = (const float*)d_in[12];
    const float* b2      = (const float*)d_in[13];
    const float* W3      = (const float*)d_in[14];
    const float* b3      = (const float*)d_in[15];
    float* out = (float*)d_out;

    float *pS, *pV, *pO, *pL, *pR1, *pR2;
    cudaGetSymbolAddress((void**)&pS,  g_S);
    cudaGetSymbolAddress((void**)&pV,  g_V);
    cudaGetSymbolAddress((void**)&pO,  g_O);
    cudaGetSymbolAddress((void**)&pL,  g_L);
    cudaGetSymbolAddress((void**)&pR1, g_R1);
    cudaGetSymbolAddress((void**)&pR2, g_R2);

    // Phase 1: phrase embeddings
    embed_kernel<<<B_SZ, 128>>>(subj_id, subj_w, emb, pS);
    embed_kernel<<<B_SZ, 128>>>(verb_id, verb_w, emb, pV);
    embed_kernel<<<B_SZ, 128>>>(obj_id,  obj_w,  emb, pO);

    dim3 lin_grid(B_SZ / 16, K_SZ / 16);
    dim3 bil_grid(B_SZ / BT, K_SZ);

    // Phase 2: r1 = tanh(bilinear(t1, s, v) + [s;v]W1^T + b1)
    linear_kernel<<<lin_grid, 256>>>(pS, pV, W1, b1, pL, D_SZ);
    bilinear_kernel<<<bil_grid, 256>>>(t1, pS, pV, pL, pR1, D_SZ, D_SZ);

    // Phase 3: r2 = tanh(bilinear(t2, v, o) + [v;o]W2^T + b2)
    linear_kernel<<<lin_grid, 256>>>(pV, pO, W2, b2, pL, D_SZ);
    bilinear_kernel<<<bil_grid, 256>>>(t2, pV, pO, pL, pR2, D_SZ, D_SZ);

    // Phase 4: r3 = tanh(bilinear(t3, r1, r2) + [r1;r2]W3^T + b3)
    linear_kernel<<<lin_grid, 256>>>(pR1, pR2, W3, b3, pL, K_SZ);
    bilinear_kernel<<<bil_grid, 256>>>(t3, pR1, pR2, pL, out, K_SZ, K_SZ);
}

// round 2
// speedup vs baseline: 1.0004x; 1.0004x over previous
#include <cuda_runtime.h>
#include <cuda_bf16.h>
#include <math.h>

// Problem constants
#define B_SZ   4096
#define D_SZ   512
#define K_SZ   256
#define N_SZ   8

// Bilinear tile config
#define BT 128   // batch rows per CTA
#define JT 128   // j-columns per tile
#define CK 16    // i-reduction chunk

// ---------------------------------------------------------------------------
// Scratch (device globals; no allocations allowed)
// ---------------------------------------------------------------------------
__device__ __align__(16) float g_S[B_SZ * D_SZ];   // subj phrase embed
__device__ __align__(16) float g_V[B_SZ * D_SZ];   // verb
__device__ __align__(16) float g_O[B_SZ * D_SZ];   // obj
__device__ __align__(16) float g_L[B_SZ * K_SZ];   // linear-term buffer (reused 3x)
__device__ __align__(16) float g_R1[B_SZ * K_SZ];
__device__ __align__(16) float g_R2[B_SZ * K_SZ];

// ---------------------------------------------------------------------------
// Packed f32x2 helpers (Blackwell FFMA2 — only reachable via PTX)
// ---------------------------------------------------------------------------
__device__ __forceinline__ void ffma2(unsigned long long& d,
                                      const unsigned long long a,
                                      const unsigned long long b) {
    asm("fma.rn.f32x2 %0, %1, %2, %0;" : "+l"(d) : "l"(a), "l"(b));
}

__device__ __forceinline__ unsigned long long splat2(float x) {
    unsigned long long r;
    unsigned int u = __float_as_uint(x);
    asm("mov.b64 %0, {%1, %1};" : "=l"(r) : "r"(u));
    return r;
}

// ---------------------------------------------------------------------------
// Kernel 1: phrase embedding  out[b,:] = sum_n w[b,n] * emb[ids[b,n],:]
// grid = B, block = 128 (one float4 per thread over D=512)
// ---------------------------------------------------------------------------
__global__ void embed_kernel(const int* __restrict__ ids,
                             const float* __restrict__ w,
                             const float* __restrict__ emb,
                             float* __restrict__ out) {
    int b = blockIdx.x;
    int t = threadIdx.x;  // 0..127
    const float4* emb4 = (const float4*)emb;
    float4 acc = make_float4(0.f, 0.f, 0.f, 0.f);
#pragma unroll
    for (int n = 0; n < N_SZ; n++) {
        int   id = __ldg(&ids[b * N_SZ + n]);
        float wn = __ldg(&w[b * N_SZ + n]);
        float4 e = __ldg(&emb4[(size_t)id * (D_SZ / 4) + t]);
        acc.x = fmaf(wn, e.x, acc.x);
        acc.y = fmaf(wn, e.y, acc.y);
        acc.z = fmaf(wn, e.z, acc.z);
        acc.w = fmaf(wn, e.w, acc.w);
    }
    ((float4*)out)[(size_t)b * (D_SZ / 4) + t] = acc;
}

// ---------------------------------------------------------------------------
// Kernel 2: linear term  L[b,k] = bias[k] + sum_d X1[b,d]W[k,d] + X2[b,d]W[k,D1+d]
// grid = (B/16, K/16), block = 256; each thread one output.
// ---------------------------------------------------------------------------
__global__ __launch_bounds__(256)
void linear_kernel(const float* __restrict__ X1, const float* __restrict__ X2,
                   const float* __restrict__ W, const float* __restrict__ bias,
                   float* __restrict__ L, int D1) {
    __shared__ float Xs[16][68];
    __shared__ float Ws[16][68];
    int tid = threadIdx.x;
    int tb = tid >> 4, tk = tid & 15;
    int b0 = blockIdx.x * 16, k0 = blockIdx.y * 16;
    int lr = tid >> 4;
    int lc = (tid & 15) * 4;
    float acc = 0.f;
#pragma unroll
    for (int h = 0; h < 2; h++) {
        const float* X = h ? X2 : X1;
        int woff = h * D1;
        for (int dc = 0; dc < D1; dc += 64) {
            __syncthreads();
            *(float4*)&Xs[lr][lc] =
                *(const float4*)&X[(size_t)(b0 + lr) * D1 + dc + lc];
            *(float4*)&Ws[lr][lc] =
                *(const float4*)&W[(size_t)(k0 + lr) * (2 * D1) + woff + dc + lc];
            __syncthreads();
#pragma unroll
            for (int d = 0; d < 64; d++)
                acc = fmaf(Xs[tb][d], Ws[tk][d], acc);
        }
    }
    L[(size_t)(b0 + tb) * K_SZ + (k0 + tk)] = acc + __ldg(&bias[k0 + tk]);
}

// ---------------------------------------------------------------------------
// Kernel 3: fused bilinear + linear + tanh
//   OUT[b,k] = tanh( sum_{i,j} X1[b,i] * T[k,i,j] * X2[b,j]  +  L[b,k] )
// grid = (B/BT, K). Per CTA: GEMM tile (128 b x 128 j) over i, epilogue
// weights by X2[b,j] and reduces over j. Inner loop uses packed FFMA2.
// ---------------------------------------------------------------------------
__global__ __launch_bounds__(256, 2)
void bilinear_kernel(const float* __restrict__ T, const float* __restrict__ X1,
                     const float* __restrict__ X2, const float* __restrict__ L,
                     float* __restrict__ OUT, int Di, int Dj) {
    __shared__ __align__(16) float As[CK][BT + 4];  // X1 chunk, transposed [i][b]
    __shared__ __align__(16) float Bs[CK][JT];      // T chunk [i][j]

    int tid = threadIdx.x;
    int tx = tid & 15, ty = tid >> 4;
    int k = blockIdx.y;
    int b0 = blockIdx.x * BT;
    const float* Tk = T + (size_t)k * Di * Dj;

    float yacc[8];
#pragma unroll
    for (int i = 0; i < 8; i++) yacc[i] = 0.f;

    for (int jt = 0; jt < Dj; jt += JT) {
        unsigned long long c2[8][4];  // 8 b-rows x 8 j-cols (packed f32x2)
#pragma unroll
        for (int i = 0; i < 8; i++)
#pragma unroll
            for (int j = 0; j < 4; j++) c2[i][j] = 0ull;

        for (int ic = 0; ic < Di; ic += CK) {
            __syncthreads();
#pragma unroll
            for (int l = 0; l < 8; l++) {  // load X1 chunk (2048 elems)
                int idx = tid + l * 256;
                int bb = idx >> 4, ii = idx & 15;
                As[ii][bb] = X1[(size_t)(b0 + bb) * Di + ic + ii];
            }
#pragma unroll
            for (int l = 0; l < 8; l++) {  // load T chunk (2048 elems)
                int idx = tid + l * 256;
                int rr = idx >> 7, cc = idx & 127;
                Bs[rr][cc] = Tk[(size_t)(ic + rr) * Dj + jt + cc];
            }
            __syncthreads();
#pragma unroll
            for (int kk = 0; kk < CK; kk++) {
                ulonglong2 bp0 = *(const ulonglong2*)&Bs[kk][tx * 8];
                ulonglong2 bp1 = *(const ulonglong2*)&Bs[kk][tx * 8 + 4];
                unsigned long long bv0 = bp0.x, bv1 = bp0.y;
                unsigned long long bv2 = bp1.x, bv3 = bp1.y;
#pragma unroll
                for (int i = 0; i < 8; i++) {
                    unsigned long long a2 = splat2(As[kk][ty * 8 + i]);
                    ffma2(c2[i][0], a2, bv0);
                    ffma2(c2[i][1], a2, bv1);
                    ffma2(c2[i][2], a2, bv2);
                    ffma2(c2[i][3], a2, bv3);
                }
            }
        }
        // epilogue: yacc[b] += sum_j C[b,j] * X2[b,j]
#pragma unroll
        for (int i = 0; i < 8; i++) {
            const float* vrow =
                &X2[(size_t)(b0 + ty * 8 + i) * Dj + jt + tx * 8];
            float4 v0 = __ldg((const float4*)vrow);
            float4 v1 = __ldg((const float4*)(vrow + 4));
            float vv[8] = {v0.x, v0.y, v0.z, v0.w, v1.x, v1.y, v1.z, v1.w};
#pragma unroll
            for (int jp = 0; jp < 4; jp++) {
                float lo = __uint_as_float((unsigned int)(c2[i][jp]));
                float hi = __uint_as_float((unsigned int)(c2[i][jp] >> 32));
                yacc[i] = fmaf(lo, vv[2 * jp], yacc[i]);
                yacc[i] = fmaf(hi, vv[2 * jp + 1], yacc[i]);
            }
        }
    }

    // reduce over tx (16 lanes per b-row group)
#pragma unroll
    for (int off = 8; off >= 1; off >>= 1)
#pragma unroll
        for (int i = 0; i < 8; i++)
            yacc[i] += __shfl_xor_sync(0xffffffffu, yacc[i], off, 16);

    if (tx == 0) {
#pragma unroll
        for (int i = 0; i < 8; i++) {
            size_t b = (size_t)b0 + ty * 8 + i;
            OUT[b * K_SZ + k] = tanhf(yacc[i] + L[b * K_SZ + k]);
        }
    }
}

// ---------------------------------------------------------------------------
// Launch
// ---------------------------------------------------------------------------
extern "C" void kernel_launch(void* const* d_in, const int* in_sizes, int n_in,
                              void* d_out, int out_size) {
    const int*   subj_id = (const int*)d_in[0];
    const float* subj_w  = (const float*)d_in[1];
    const int*   verb_id = (const int*)d_in[2];
    const float* verb_w  = (const float*)d_in[3];
    const int*   obj_id  = (const int*)d_in[4];
    const float* obj_w   = (const float*)d_in[5];
    const float* emb     = (const float*)d_in[6];
    const float* t1      = (const float*)d_in[7];
    const float* t2      = (const float*)d_in[8];
    const float* t3      = (const float*)d_in[9];
    const float* W1      = (const float*)d_in[10];
    const float* b1      = (const float*)d_in[11];
    const float* W2      = (const float*)d_in[12];
    const float* b2      = (const float*)d_in[13];
    const float* W3      = (const float*)d_in[14];
    const float* b3      = (const float*)d_in[15];
    float* out = (float*)d_out;

    float *pS, *pV, *pO, *pL, *pR1, *pR2;
    cudaGetSymbolAddress((void**)&pS,  g_S);
    cudaGetSymbolAddress((void**)&pV,  g_V);
    cudaGetSymbolAddress((void**)&pO,  g_O);
    cudaGetSymbolAddress((void**)&pL,  g_L);
    cudaGetSymbolAddress((void**)&pR1, g_R1);
    cudaGetSymbolAddress((void**)&pR2, g_R2);

    // Phase 1: phrase embeddings
    embed_kernel<<<B_SZ, 128>>>(subj_id, subj_w, emb, pS);
    embed_kernel<<<B_SZ, 128>>>(verb_id, verb_w, emb, pV);
    embed_kernel<<<B_SZ, 128>>>(obj_id,  obj_w,  emb, pO);

    dim3 lin_grid(B_SZ / 16, K_SZ / 16);
    dim3 bil_grid(B_SZ / BT, K_SZ);

    // Phase 2: r1 = tanh(bilinear(t1, s, v) + [s;v]W1^T + b1)
    linear_kernel<<<lin_grid, 256>>>(pS, pV, W1, b1, pL, D_SZ);
    bilinear_kernel<<<bil_grid, 256>>>(t1, pS, pV, pL, pR1, D_SZ, D_SZ);

    // Phase 3: r2 = tanh(bilinear(t2, v, o) + [v;o]W2^T + b2)
    linear_kernel<<<lin_grid, 256>>>(pV, pO, W2, b2, pL, D_SZ);
    bilinear_kernel<<<bil_grid, 256>>>(t2, pV, pO, pL, pR2, D_SZ, D_SZ);

    // Phase 4: r3 = tanh(bilinear(t3, r1, r2) + [r1;r2]W3^T + b3)
    linear_kernel<<<lin_grid, 256>>>(pR1, pR2, W3, b3, pL, K_SZ);
    bilinear_kernel<<<bil_grid, 256>>>(t3, pR1, pR2, pL, out, K_SZ, K_SZ);
}

// round 4
// speedup vs baseline: 2.4070x; 2.4060x over previous
#include <cuda_runtime.h>
#include <math.h>
#include <stdint.h>

#define B_SZ 4096
#define K_SZ 256
#define N_SZ 8

// ---------------------------------------------------------------------------
// Scratch (device globals; no allocations allowed)
// ---------------------------------------------------------------------------
__device__ __align__(256) float g_S[B_SZ * 512];
__device__ __align__(256) float g_V[B_SZ * 512];
__device__ __align__(256) float g_O[B_SZ * 512];
__device__ __align__(256) float g_L[B_SZ * 256];
__device__ __align__(256) float g_R1[B_SZ * 256];
__device__ __align__(256) float g_R2[B_SZ * 256];

// ---------------------------------------------------------------------------
// Generic-PTX helpers (NO arch-specific 'a' instructions — harness compiles
// via compute_103 virtual arch, so tcgen05/TMEM are unavailable)
// ---------------------------------------------------------------------------
__device__ __forceinline__ uint32_t smem_u32(const void* p) {
    uint32_t a;
    asm("{ .reg .u64 t; cvta.to.shared.u64 t, %1; cvt.u32.u64 %0, t; }"
        : "=r"(a) : "l"(p));
    return a;
}
__device__ __forceinline__ float to_tf32(float x) {
    float r;
    asm("cvt.rna.tf32.f32 %0, %1;" : "=f"(r) : "f"(x));
    return r;
}
__device__ __forceinline__ void ldm4(uint32_t* r, uint32_t addr) {
    asm volatile(
        "ldmatrix.sync.aligned.m8n8.x4.shared.b16 {%0,%1,%2,%3}, [%4];"
        : "=r"(r[0]), "=r"(r[1]), "=r"(r[2]), "=r"(r[3]) : "r"(addr));
}
__device__ __forceinline__ void mma_tf32(float* c, const uint32_t* a,
                                         uint32_t b0, uint32_t b1) {
    asm volatile(
        "mma.sync.aligned.m16n8k8.row.col.f32.tf32.tf32.f32 "
        "{%0,%1,%2,%3}, {%4,%5,%6,%7}, {%8,%9}, {%0,%1,%2,%3};"
        : "+f"(c[0]), "+f"(c[1]), "+f"(c[2]), "+f"(c[3])
        : "r"(a[0]), "r"(a[1]), "r"(a[2]), "r"(a[3]), "r"(b0), "r"(b1));
}

// ---------------------------------------------------------------------------
// Kernel 1: phrase embedding
// ---------------------------------------------------------------------------
__global__ void embed_kernel(const int* __restrict__ ids,
                             const float* __restrict__ w,
                             const float* __restrict__ emb,
                             float* __restrict__ out) {
    int b = blockIdx.x;
    int t = threadIdx.x;
    const float4* emb4 = (const float4*)emb;
    float4 acc = make_float4(0.f, 0.f, 0.f, 0.f);
#pragma unroll
    for (int n = 0; n < N_SZ; n++) {
        int   id = __ldg(&ids[b * N_SZ + n]);
        float wn = __ldg(&w[b * N_SZ + n]);
        float4 e = __ldg(&emb4[(size_t)id * 128 + t]);
        acc.x = fmaf(wn, e.x, acc.x);
        acc.y = fmaf(wn, e.y, acc.y);
        acc.z = fmaf(wn, e.z, acc.z);
        acc.w = fmaf(wn, e.w, acc.w);
    }
    ((float4*)out)[(size_t)b * 128 + t] = acc;
}

// ---------------------------------------------------------------------------
// Kernel 2: linear term (SIMT; ~200us each, revisit once bilinears dominate)
// ---------------------------------------------------------------------------
__global__ __launch_bounds__(256)
void linear_kernel(const float* __restrict__ X1, const float* __restrict__ X2,
                   const float* __restrict__ W, const float* __restrict__ bias,
                   float* __restrict__ L, int D1) {
    __shared__ float Xs[16][68];
    __shared__ float Ws[16][68];
    int tid = threadIdx.x;
    int tb = tid >> 4, tk = tid & 15;
    int b0 = blockIdx.x * 16, k0 = blockIdx.y * 16;
    int lr = tid >> 4;
    int lc = (tid & 15) * 4;
    float acc = 0.f;
#pragma unroll
    for (int h = 0; h < 2; h++) {
        const float* X = h ? X2 : X1;
        int woff = h * D1;
        for (int dc = 0; dc < D1; dc += 64) {
            __syncthreads();
            *(float4*)&Xs[lr][lc] =
                *(const float4*)&X[(size_t)(b0 + lr) * D1 + dc + lc];
            *(float4*)&Ws[lr][lc] =
                *(const float4*)&W[(size_t)(k0 + lr) * (2 * D1) + woff + dc + lc];
            __syncthreads();
#pragma unroll
            for (int d = 0; d < 64; d++)
                acc = fmaf(Xs[tb][d], Ws[tk][d], acc);
        }
    }
    L[(size_t)(b0 + tb) * K_SZ + (k0 + tk)] = acc + __ldg(&bias[k0 + tk]);
}

// ---------------------------------------------------------------------------
// Kernel 3: tensor-core (mma.sync tf32) fused bilinear + tanh
//   C[b,i] = sum_j X2[b,j]*T[k,i,j]   (tf32 MMA over j, fp32 acc in regs)
//   OUT[b,k] = tanh( sum_i X1[b,i]*C[b,i] + L[b,k] )
// grid = (B/128, K). block = 256 (8 warps; warp w owns b-rows w*16..w*16+15).
// i processed in chunks of 128 (per-warp n128 accumulators, 64 regs),
// j in chunks of 16 through a double-buffered SMEM pipeline.
// ---------------------------------------------------------------------------
#define IC 128
#define JC 16
#define SSTR 20  // SMEM row stride in words (16 data + 4 pad -> conflict-free ldmatrix)

template <int DI, int DJ>
__global__ void __launch_bounds__(256, 2)
bilinear_mma(const float* __restrict__ T, const float* __restrict__ X1,
             const float* __restrict__ X2, const float* __restrict__ L,
             float* __restrict__ OUT) {
    __shared__ float As[2][128 * SSTR];  // X2 chunk [b=128][j=16]
    __shared__ float Bs[2][128 * SSTR];  // T  chunk [i=128][j=16]

    const int tid  = threadIdx.x;
    const int w    = tid >> 5;
    const int lane = tid & 31;
    const int b0   = blockIdx.x * 128;
    const int k    = blockIdx.y;
    const float* Tk = T + (size_t)k * DI * DJ;

    // staging: 512 float4-slots per tile; thread handles slots tid, tid+256
    const int r0 = tid >> 2;          // rows 0..63
    const int r1 = 64 + r0;           // rows 64..127
    const int jq = (tid & 3) * 4;     // word offset within 16-j chunk

    // ldmatrix source addresses (within a buffer), lane-dependent:
    // x4 groups g=lane>>3: row += (g&1)*8, colword += (g&2)*2
    const int lg  = lane >> 3;
    const int lr8 = lane & 7;
    const int ld_row_off = (lg & 1) * 8;
    const int ld_col_off = (lg & 2) * 2;
    uint32_t a_base0 = smem_u32(&As[0][0]) +
        ((w * 16 + lr8 + ld_row_off) * SSTR + ld_col_off) * 4;
    uint32_t b_base0 = smem_u32(&Bs[0][0]) +
        ((lr8 + ld_row_off) * SSTR + ld_col_off) * 4;
    const uint32_t bufstep = 128 * SSTR * 4;

    const int er = lane >> 2;        // epilogue row within slab
    const int ec = lane & 3;         // epilogue col quad
    const size_t bgr = (size_t)b0 + w * 16 + er;

    float y0 = 0.f, y1 = 0.f;

    for (int ic = 0; ic < DI / IC; ic++) {
        const int i0 = ic * IC;
        float acc[16][4];
#pragma unroll
        for (int nt = 0; nt < 16; nt++)
#pragma unroll
            for (int q = 0; q < 4; q++) acc[nt][q] = 0.f;

        // prefetch j-chunk 0
        float4 pa0 = __ldg((const float4*)&X2[(size_t)(b0 + r0) * DJ + jq]);
        float4 pa1 = __ldg((const float4*)&X2[(size_t)(b0 + r1) * DJ + jq]);
        float4 pb0 = __ldg((const float4*)&Tk[(size_t)(i0 + r0) * DJ + jq]);
        float4 pb1 = __ldg((const float4*)&Tk[(size_t)(i0 + r1) * DJ + jq]);

        for (int c = 0; c < DJ / JC; c++) {
            const int buf = c & 1;
            float* Ab = As[buf];
            float* Bb = Bs[buf];
            // store with round-to-nearest tf32 conversion
            Ab[r0 * SSTR + jq + 0] = to_tf32(pa0.x);
            Ab[r0 * SSTR + jq + 1] = to_tf32(pa0.y);
            Ab[r0 * SSTR + jq + 2] = to_tf32(pa0.z);
            Ab[r0 * SSTR + jq + 3] = to_tf32(pa0.w);
            Ab[r1 * SSTR + jq + 0] = to_tf32(pa1.x);
            Ab[r1 * SSTR + jq + 1] = to_tf32(pa1.y);
            Ab[r1 * SSTR + jq + 2] = to_tf32(pa1.z);
            Ab[r1 * SSTR + jq + 3] = to_tf32(pa1.w);
            Bb[r0 * SSTR + jq + 0] = to_tf32(pb0.x);
            Bb[r0 * SSTR + jq + 1] = to_tf32(pb0.y);
            Bb[r0 * SSTR + jq + 2] = to_tf32(pb0.z);
            Bb[r0 * SSTR + jq + 3] = to_tf32(pb0.w);
            Bb[r1 * SSTR + jq + 0] = to_tf32(pb1.x);
            Bb[r1 * SSTR + jq + 1] = to_tf32(pb1.y);
            Bb[r1 * SSTR + jq + 2] = to_tf32(pb1.z);
            Bb[r1 * SSTR + jq + 3] = to_tf32(pb1.w);
            __syncthreads();

            // prefetch next chunk while computing this one
            if (c + 1 < DJ / JC) {
                const int j0 = (c + 1) * JC;
                pa0 = __ldg((const float4*)&X2[(size_t)(b0 + r0) * DJ + j0 + jq]);
                pa1 = __ldg((const float4*)&X2[(size_t)(b0 + r1) * DJ + j0 + jq]);
                pb0 = __ldg((const float4*)&Tk[(size_t)(i0 + r0) * DJ + j0 + jq]);
                pb1 = __ldg((const float4*)&Tk[(size_t)(i0 + r1) * DJ + j0 + jq]);
            }

            // A fragments for both k-steps
            uint32_t a[2][4];
            ldm4(a[0], a_base0 + buf * bufstep);
            ldm4(a[1], a_base0 + buf * bufstep + 8 * 4);

#pragma unroll
            for (int s = 0; s < 2; s++) {
                uint32_t bb = b_base0 + buf * bufstep + s * 8 * 4;
#pragma unroll
                for (int t2 = 0; t2 < 8; t2++) {
                    uint32_t br[4];
                    ldm4(br, bb + (t2 * 16) * SSTR * 4);
                    mma_tf32(acc[2 * t2],     a[s], br[0], br[2]);
                    mma_tf32(acc[2 * t2 + 1], a[s], br[1], br[3]);
                }
            }
        }
        __syncthreads();

        // epilogue: y[b] += sum_{i in chunk} X1[b,i] * C[b,i]
#pragma unroll
        for (int nt = 0; nt < 16; nt++) {
            const int ii = i0 + nt * 8 + ec * 2;
            float2 xa = __ldg((const float2*)&X1[bgr * DI + ii]);
            float2 xb = __ldg((const float2*)&X1[(bgr + 8) * DI + ii]);
            y0 = fmaf(acc[nt][0], xa.x, y0);
            y0 = fmaf(acc[nt][1], xa.y, y0);
            y1 = fmaf(acc[nt][2], xb.x, y1);
            y1 = fmaf(acc[nt][3], xb.y, y1);
        }
    }

    // reduce over the 4 column-quad lanes (lane bits 0-1)
    y0 += __shfl_xor_sync(0xffffffffu, y0, 1);
    y0 += __shfl_xor_sync(0xffffffffu, y0, 2);
    y1 += __shfl_xor_sync(0xffffffffu, y1, 1);
    y1 += __shfl_xor_sync(0xffffffffu, y1, 2);

    if (ec == 0) {
        OUT[bgr * K_SZ + k]       = tanhf(y0 + L[bgr * K_SZ + k]);
        OUT[(bgr + 8) * K_SZ + k] = tanhf(y1 + L[(bgr + 8) * K_SZ + k]);
    }
}

// ---------------------------------------------------------------------------
// Launch
// ---------------------------------------------------------------------------
extern "C" void kernel_launch(void* const* d_in, const int* in_sizes, int n_in,
                              void* d_out, int out_size) {
    const int*   subj_id = (const int*)d_in[0];
    const float* subj_w  = (const float*)d_in[1];
    const int*   verb_id = (const int*)d_in[2];
    const float* verb_w  = (const float*)d_in[3];
    const int*   obj_id  = (const int*)d_in[4];
    const float* obj_w   = (const float*)d_in[5];
    const float* emb     = (const float*)d_in[6];
    const float* t1      = (const float*)d_in[7];
    const float* t2      = (const float*)d_in[8];
    const float* t3      = (const float*)d_in[9];
    const float* W1      = (const float*)d_in[10];
    const float* b1      = (const float*)d_in[11];
    const float* W2      = (const float*)d_in[12];
    const float* b2      = (const float*)d_in[13];
    const float* W3      = (const float*)d_in[14];
    const float* b3      = (const float*)d_in[15];
    float* out = (float*)d_out;

    float *pS, *pV, *pO, *pL, *pR1, *pR2;
    cudaGetSymbolAddress((void**)&pS,  g_S);
    cudaGetSymbolAddress((void**)&pV,  g_V);
    cudaGetSymbolAddress((void**)&pO,  g_O);
    cudaGetSymbolAddress((void**)&pL,  g_L);
    cudaGetSymbolAddress((void**)&pR1, g_R1);
    cudaGetSymbolAddress((void**)&pR2, g_R2);

    // Phase 1: phrase embeddings
    embed_kernel<<<B_SZ, 128>>>(subj_id, subj_w, emb, pS);
    embed_kernel<<<B_SZ, 128>>>(verb_id, verb_w, emb, pV);
    embed_kernel<<<B_SZ, 128>>>(obj_id,  obj_w,  emb, pO);

    dim3 lin_grid(B_SZ / 16, K_SZ / 16);
    dim3 bil_grid(B_SZ / 128, K_SZ);  // x fast -> 32 CTAs share T[k] in L2

    // Phase 2: r1
    linear_kernel<<<lin_grid, 256>>>(pS, pV, W1, b1, pL, 512);
    bilinear_mma<512, 512><<<bil_grid, 256>>>(t1, pS, pV, pL, pR1);

    // Phase 3: r2
    linear_kernel<<<lin_grid, 256>>>(pV, pO, W2, b2, pL, 512);
    bilinear_mma<512, 512><<<bil_grid, 256>>>(t2, pV, pO, pL, pR2);

    // Phase 4: r3
    linear_kernel<<<lin_grid, 256>>>(pR1, pR2, W3, b3, pL, 256);
    bilinear_mma<256, 256><<<bil_grid, 256>>>(t3, pR1, pR2, pL, out);
}

// round 5
// speedup vs baseline: 6.1920x; 2.5725x over previous
#include <cuda_runtime.h>
#include <cuda_fp16.h>
#include <math.h>
#include <stdint.h>

#define B_SZ 4096
#define K_SZ 256
#define N_SZ 8

// ---------------------------------------------------------------------------
// Scratch (device globals; allocations are banned)
// ---------------------------------------------------------------------------
__device__ __align__(256) float  g_S[B_SZ * 512];
__device__ __align__(256) float  g_V[B_SZ * 512];
__device__ __align__(256) float  g_O[B_SZ * 512];
__device__ __align__(256) float  g_L[B_SZ * 256];
__device__ __align__(256) float  g_R1[B_SZ * 256];
__device__ __align__(256) float  g_R2[B_SZ * 256];
__device__ __align__(256) __half g_Sh[B_SZ * 512];
__device__ __align__(256) __half g_Vh[B_SZ * 512];
__device__ __align__(256) __half g_Oh[B_SZ * 512];
__device__ __align__(256) __half g_R1h[B_SZ * 256];
__device__ __align__(256) __half g_R2h[B_SZ * 256];
__device__ __align__(256) __half g_T1h[256u * 512u * 512u];
__device__ __align__(256) __half g_T2h[256u * 512u * 512u];
__device__ __align__(256) __half g_T3h[256u * 256u * 256u];
__device__ __align__(256) __half g_W1h[256 * 1024];
__device__ __align__(256) __half g_W2h[256 * 1024];
__device__ __align__(256) __half g_W3h[256 * 512];

// ---------------------------------------------------------------------------
// Generic-PTX helpers (compute_103 virtual arch: no tcgen05/'a' features)
// ---------------------------------------------------------------------------
__device__ __forceinline__ uint32_t smem_u32(const void* p) {
    uint32_t a;
    asm("{ .reg .u64 t; cvta.to.shared.u64 t, %1; cvt.u32.u64 %0, t; }"
        : "=r"(a) : "l"(p));
    return a;
}
__device__ __forceinline__ void ldm4(uint32_t* r, uint32_t addr) {
    asm volatile(
        "ldmatrix.sync.aligned.m8n8.x4.shared.b16 {%0,%1,%2,%3}, [%4];"
        : "=r"(r[0]), "=r"(r[1]), "=r"(r[2]), "=r"(r[3]) : "r"(addr));
}
__device__ __forceinline__ void mma_f16(float* c, const uint32_t* a,
                                        uint32_t b0, uint32_t b1) {
    asm volatile(
        "mma.sync.aligned.m16n8k16.row.col.f32.f16.f16.f32 "
        "{%0,%1,%2,%3}, {%4,%5,%6,%7}, {%8,%9}, {%0,%1,%2,%3};"
        : "+f"(c[0]), "+f"(c[1]), "+f"(c[2]), "+f"(c[3])
        : "r"(a[0]), "r"(a[1]), "r"(a[2]), "r"(a[3]), "r"(b0), "r"(b1));
}
__device__ __forceinline__ void cp16(uint32_t dst, const void* src) {
    asm volatile("cp.async.ca.shared.global [%0], [%1], 16;"
                 :: "r"(dst), "l"(src) : "memory");
}
#define CP_COMMIT() asm volatile("cp.async.commit_group;" ::: "memory")
template <int N>
__device__ __forceinline__ void cp_wait() {
    asm volatile("cp.async.wait_group %0;" :: "n"(N) : "memory");
}

#define HSTR 40  // halfs per SMEM row: 32 data + 8 pad (80B stride, conflict-free)

// ---------------------------------------------------------------------------
// fp32 -> fp16 bulk convert
// ---------------------------------------------------------------------------
__global__ void f2h_kernel(const float* __restrict__ src,
                           __half* __restrict__ dst, int n) {
    int i = (blockIdx.x * blockDim.x + threadIdx.x) * 4;
    int stride = gridDim.x * blockDim.x * 4;
    for (; i < n; i += stride) {
        float4 v = *(const float4*)(src + i);
        __half2 h0 = __floats2half2_rn(v.x, v.y);
        __half2 h1 = __floats2half2_rn(v.z, v.w);
        ((__half2*)(dst + i))[0] = h0;
        ((__half2*)(dst + i))[1] = h1;
    }
}

// ---------------------------------------------------------------------------
// phrase embedding (fp32 + fp16 outputs)
// ---------------------------------------------------------------------------
__global__ void embed_kernel(const int* __restrict__ ids,
                             const float* __restrict__ w,
                             const float* __restrict__ emb,
                             float* __restrict__ out,
                             __half* __restrict__ outh) {
    int b = blockIdx.x;
    int t = threadIdx.x;
    const float4* emb4 = (const float4*)emb;
    float4 acc = make_float4(0.f, 0.f, 0.f, 0.f);
#pragma unroll
    for (int n = 0; n < N_SZ; n++) {
        int   id = __ldg(&ids[b * N_SZ + n]);
        float wn = __ldg(&w[b * N_SZ + n]);
        float4 e = __ldg(&emb4[(size_t)id * 128 + t]);
        acc.x = fmaf(wn, e.x, acc.x);
        acc.y = fmaf(wn, e.y, acc.y);
        acc.z = fmaf(wn, e.z, acc.z);
        acc.w = fmaf(wn, e.w, acc.w);
    }
    ((float4*)out)[(size_t)b * 128 + t] = acc;
    ((__half2*)outh)[(size_t)b * 256 + t * 2]     = __floats2half2_rn(acc.x, acc.y);
    ((__half2*)outh)[(size_t)b * 256 + t * 2 + 1] = __floats2half2_rn(acc.z, acc.w);
}

// ---------------------------------------------------------------------------
// linear term via fp16 mma: L[b,k] = bias[k] + [X1;X2][b,:] . W[k,:]
// CTA tile 64b x 128k, 8 warps (2x4), warp tile 32x32. grid (B/64, K/128).
// ---------------------------------------------------------------------------
__global__ void __launch_bounds__(256, 2)
linear_f16(const __half* __restrict__ X1h, const __half* __restrict__ X2h,
           const __half* __restrict__ Wh, const float* __restrict__ bias,
           float* __restrict__ L, int Dh) {
    __shared__ __align__(16) __half Abuf[2][64 * HSTR];
    __shared__ __align__(16) __half Bbuf[2][128 * HSTR];

    const int tid = threadIdx.x, lane = tid & 31, w = tid >> 5;
    const int wm = w >> 2, wn = w & 3;
    const int b0 = blockIdx.x * 64, k0 = blockIdx.y * 128;
    const int g = lane >> 3, lr = lane & 7;
    const int a_row = (g & 1) * 8 + lr, a_col = (g >> 1) * 8;
    const int b_row = (g >> 1) * 8 + lr, b_col = (g & 1) * 8;

    uint32_t a_addr[2], b_addr[2];
#pragma unroll
    for (int buf = 0; buf < 2; buf++) {
        a_addr[buf] = smem_u32(&Abuf[buf][(wm * 32 + a_row) * HSTR + a_col]);
        b_addr[buf] = smem_u32(&Bbuf[buf][(wn * 32 + b_row) * HSTR + b_col]);
    }

    float acc[2][4][4];
#pragma unroll
    for (int mt = 0; mt < 2; mt++)
#pragma unroll
        for (int nt = 0; nt < 4; nt++)
#pragma unroll
            for (int q = 0; q < 4; q++) acc[mt][nt][q] = 0.f;

    const int HC = Dh / 32;
    const int NC = 2 * HC;
    const int srow = tid >> 2, sseg = (tid & 3) * 8;

    // stage chunk c into buffer nb
    auto stage = [&](int c, int nb) {
        const __half* Asrc = (c < HC) ? X1h : X2h;
        int dof = ((c < HC) ? c : c - HC) * 32;
        cp16(smem_u32(&Abuf[nb][srow * HSTR + sseg]),
             Asrc + (size_t)(b0 + srow) * Dh + dof + sseg);
        cp16(smem_u32(&Bbuf[nb][srow * HSTR + sseg]),
             Wh + (size_t)(k0 + srow) * (2 * Dh) + c * 32 + sseg);
        cp16(smem_u32(&Bbuf[nb][(srow + 64) * HSTR + sseg]),
             Wh + (size_t)(k0 + srow + 64) * (2 * Dh) + c * 32 + sseg);
    };

    stage(0, 0);
    CP_COMMIT();
    for (int c = 0; c < NC; c++) {
        if (c + 1 < NC) {
            stage(c + 1, (c + 1) & 1);
            CP_COMMIT();
            cp_wait<1>();
        } else {
            cp_wait<0>();
        }
        __syncthreads();
        int buf = c & 1;
#pragma unroll
        for (int ks = 0; ks < 2; ks++) {
            uint32_t a[2][4];
            ldm4(a[0], a_addr[buf] + (0 * 16 * HSTR + ks * 16) * 2);
            ldm4(a[1], a_addr[buf] + (1 * 16 * HSTR + ks * 16) * 2);
            uint32_t br[2][4];
            ldm4(br[0], b_addr[buf] + (ks * 16) * 2);
            ldm4(br[1], b_addr[buf] + (16 * HSTR + ks * 16) * 2);
#pragma unroll
            for (int mt = 0; mt < 2; mt++)
#pragma unroll
                for (int nt = 0; nt < 4; nt++) {
                    const uint32_t* bb = br[nt >> 1];
                    mma_f16(acc[mt][nt], a[mt], bb[(nt & 1) * 2],
                            bb[(nt & 1) * 2 + 1]);
                }
        }
        __syncthreads();
    }

    const int er = lane >> 2, ec = lane & 3;
#pragma unroll
    for (int mt = 0; mt < 2; mt++) {
        int r = b0 + wm * 32 + mt * 16 + er;
#pragma unroll
        for (int nt = 0; nt < 4; nt++) {
            int kk = k0 + wn * 32 + nt * 8 + ec * 2;
            float bz0 = __ldg(&bias[kk]), bz1 = __ldg(&bias[kk + 1]);
            L[(size_t)r * K_SZ + kk]           = acc[mt][nt][0] + bz0;
            L[(size_t)r * K_SZ + kk + 1]       = acc[mt][nt][1] + bz1;
            L[(size_t)(r + 8) * K_SZ + kk]     = acc[mt][nt][2] + bz0;
            L[(size_t)(r + 8) * K_SZ + kk + 1] = acc[mt][nt][3] + bz1;
        }
    }
}

// ---------------------------------------------------------------------------
// fused bilinear + tanh via fp16 mma:
//   C[b,i] = sum_j X2h[b,j] * Th[k,i,j]  (m16n8k16, fp32 acc)
//   OUT[b,k] = tanh( sum_i X1[b,i]*C[b,i] + L[b,k] )
// grid (B/128, K); CTA 128b x 128i tile per i-chunk; warps 2x4, tile 64x32.
// j streamed in 32-wide cp.async double-buffered chunks.
// ---------------------------------------------------------------------------
template <int DI, int DJ>
__global__ void __launch_bounds__(256, 2)
bilinear_f16(const __half* __restrict__ Th, const float* __restrict__ X1,
             const __half* __restrict__ X2h, const float* __restrict__ L,
             float* __restrict__ OUT, __half* __restrict__ OUTh) {
    __shared__ __align__(16) __half Abuf[2][128 * HSTR];
    __shared__ __align__(16) __half Bbuf[2][128 * HSTR];
    __shared__ float ysum[128];

    const int tid = threadIdx.x, lane = tid & 31, w = tid >> 5;
    const int wm = w >> 2, wn = w & 3;
    const int b0 = blockIdx.x * 128, k = blockIdx.y;
    const __half* Tk = Th + (size_t)k * DI * DJ;

    if (tid < 128) ysum[tid] = 0.f;

    const int g = lane >> 3, lr = lane & 7;
    const int a_row = (g & 1) * 8 + lr, a_col = (g >> 1) * 8;
    const int b_row = (g >> 1) * 8 + lr, b_col = (g & 1) * 8;

    uint32_t a_addr[2], b_addr[2];
#pragma unroll
    for (int buf = 0; buf < 2; buf++) {
        a_addr[buf] = smem_u32(&Abuf[buf][(wm * 64 + a_row) * HSTR + a_col]);
        b_addr[buf] = smem_u32(&Bbuf[buf][(wn * 32 + b_row) * HSTR + b_col]);
    }

    // staging tasks: 512 segments per matrix; thread does s=tid and s=tid+256
    const int r0 = tid >> 2, seg0 = (tid & 3) * 8;
    const int r1 = (tid + 256) >> 2, seg1 = ((tid + 256) & 3) * 8;

    const int er = lane >> 2, ec = lane & 3;
    float y[2][4];
#pragma unroll
    for (int i = 0; i < 2; i++)
#pragma unroll
        for (int m = 0; m < 4; m++) y[i][m] = 0.f;

    const int NC = DJ / 32;

    for (int ich = 0; ich < DI / 128; ich++) {
        const int i0 = ich * 128;
        float acc[4][4][4];
#pragma unroll
        for (int mt = 0; mt < 4; mt++)
#pragma unroll
            for (int nt = 0; nt < 4; nt++)
#pragma unroll
                for (int q = 0; q < 4; q++) acc[mt][nt][q] = 0.f;

        auto stage = [&](int c, int nb) {
            int j0 = c * 32;
            cp16(smem_u32(&Abuf[nb][r0 * HSTR + seg0]),
                 X2h + (size_t)(b0 + r0) * DJ + j0 + seg0);
            cp16(smem_u32(&Abuf[nb][r1 * HSTR + seg1]),
                 X2h + (size_t)(b0 + r1) * DJ + j0 + seg1);
            cp16(smem_u32(&Bbuf[nb][r0 * HSTR + seg0]),
                 Tk + (size_t)(i0 + r0) * DJ + j0 + seg0);
            cp16(smem_u32(&Bbuf[nb][r1 * HSTR + seg1]),
                 Tk + (size_t)(i0 + r1) * DJ + j0 + seg1);
        };

        stage(0, 0);
        CP_COMMIT();
        for (int c = 0; c < NC; c++) {
            if (c + 1 < NC) {
                stage(c + 1, (c + 1) & 1);
                CP_COMMIT();
                cp_wait<1>();
            } else {
                cp_wait<0>();
            }
            __syncthreads();
            int buf = c & 1;
#pragma unroll
            for (int ks = 0; ks < 2; ks++) {
                uint32_t a[4][4];
#pragma unroll
                for (int mt = 0; mt < 4; mt++)
                    ldm4(a[mt], a_addr[buf] + (mt * 16 * HSTR + ks * 16) * 2);
                uint32_t br[2][4];
                ldm4(br[0], b_addr[buf] + (ks * 16) * 2);
                ldm4(br[1], b_addr[buf] + (16 * HSTR + ks * 16) * 2);
#pragma unroll
                for (int mt = 0; mt < 4; mt++)
#pragma unroll
                    for (int nt = 0; nt < 4; nt++) {
                        const uint32_t* bb = br[nt >> 1];
                        mma_f16(acc[mt][nt], a[mt], bb[(nt & 1) * 2],
                                bb[(nt & 1) * 2 + 1]);
                    }
            }
            __syncthreads();
        }

        // epilogue: fold C with fp32 X1
#pragma unroll
        for (int mt = 0; mt < 4; mt++) {
            int r = wm * 64 + mt * 16 + er;
#pragma unroll
            for (int nt = 0; nt < 4; nt++) {
                int ii = i0 + wn * 32 + nt * 8 + ec * 2;
                float2 xa = __ldg((const float2*)&X1[(size_t)(b0 + r) * DI + ii]);
                float2 xb = __ldg((const float2*)&X1[(size_t)(b0 + r + 8) * DI + ii]);
                y[0][mt] = fmaf(acc[mt][nt][0], xa.x, y[0][mt]);
                y[0][mt] = fmaf(acc[mt][nt][1], xa.y, y[0][mt]);
                y[1][mt] = fmaf(acc[mt][nt][2], xb.x, y[1][mt]);
                y[1][mt] = fmaf(acc[mt][nt][3], xb.y, y[1][mt]);
            }
        }
    }

    // reduce over column-quad lanes
#pragma unroll
    for (int i = 0; i < 2; i++)
#pragma unroll
        for (int mt = 0; mt < 4; mt++) {
            y[i][mt] += __shfl_xor_sync(0xffffffffu, y[i][mt], 1);
            y[i][mt] += __shfl_xor_sync(0xffffffffu, y[i][mt], 2);
        }
    if (ec == 0) {
#pragma unroll
        for (int mt = 0; mt < 4; mt++) {
            atomicAdd(&ysum[wm * 64 + mt * 16 + er], y[0][mt]);
            atomicAdd(&ysum[wm * 64 + mt * 16 + er + 8], y[1][mt]);
        }
    }
    __syncthreads();
    if (tid < 128) {
        size_t b = (size_t)b0 + tid;
        float v = tanhf(ysum[tid] + L[b * K_SZ + k]);
        OUT[b * K_SZ + k] = v;
        OUTh[b * K_SZ + k] = __float2half(v);
    }
}

// ---------------------------------------------------------------------------
// Launch
// ---------------------------------------------------------------------------
extern "C" void kernel_launch(void* const* d_in, const int* in_sizes, int n_in,
                              void* d_out, int out_size) {
    const int*   subj_id = (const int*)d_in[0];
    const float* subj_w  = (const float*)d_in[1];
    const int*   verb_id = (const int*)d_in[2];
    const float* verb_w  = (const float*)d_in[3];
    const int*   obj_id  = (const int*)d_in[4];
    const float* obj_w   = (const float*)d_in[5];
    const float* emb     = (const float*)d_in[6];
    const float* t1      = (const float*)d_in[7];
    const float* t2      = (const float*)d_in[8];
    const float* t3      = (const float*)d_in[9];
    const float* W1      = (const float*)d_in[10];
    const float* b1      = (const float*)d_in[11];
    const float* W2      = (const float*)d_in[12];
    const float* b2      = (const float*)d_in[13];
    const float* W3      = (const float*)d_in[14];
    const float* b3      = (const float*)d_in[15];
    float* out = (float*)d_out;

    float *pS, *pV, *pO, *pL, *pR1, *pR2;
    __half *pSh, *pVh, *pOh, *pR1h, *pR2h;
    __half *pT1h, *pT2h, *pT3h, *pW1h, *pW2h, *pW3h;
    cudaGetSymbolAddress((void**)&pS,   g_S);
    cudaGetSymbolAddress((void**)&pV,   g_V);
    cudaGetSymbolAddress((void**)&pO,   g_O);
    cudaGetSymbolAddress((void**)&pL,   g_L);
    cudaGetSymbolAddress((void**)&pR1,  g_R1);
    cudaGetSymbolAddress((void**)&pR2,  g_R2);
    cudaGetSymbolAddress((void**)&pSh,  g_Sh);
    cudaGetSymbolAddress((void**)&pVh,  g_Vh);
    cudaGetSymbolAddress((void**)&pOh,  g_Oh);
    cudaGetSymbolAddress((void**)&pR1h, g_R1h);
    cudaGetSymbolAddress((void**)&pR2h, g_R2h);
    cudaGetSymbolAddress((void**)&pT1h, g_T1h);
    cudaGetSymbolAddress((void**)&pT2h, g_T2h);
    cudaGetSymbolAddress((void**)&pT3h, g_T3h);
    cudaGetSymbolAddress((void**)&pW1h, g_W1h);
    cudaGetSymbolAddress((void**)&pW2h, g_W2h);
    cudaGetSymbolAddress((void**)&pW3h, g_W3h);

    // Phase 0: embeddings + operand conversion
    embed_kernel<<<B_SZ, 128>>>(subj_id, subj_w, emb, pS, pSh);
    embed_kernel<<<B_SZ, 128>>>(verb_id, verb_w, emb, pV, pVh);
    embed_kernel<<<B_SZ, 128>>>(obj_id,  obj_w,  emb, pO, pOh);
    f2h_kernel<<<256, 256>>>(W1, pW1h, 256 * 1024);
    f2h_kernel<<<256, 256>>>(W2, pW2h, 256 * 1024);
    f2h_kernel<<<256, 256>>>(W3, pW3h, 256 * 512);
    f2h_kernel<<<2048, 256>>>(t1, pT1h, 256 * 512 * 512);
    f2h_kernel<<<2048, 256>>>(t2, pT2h, 256 * 512 * 512);
    f2h_kernel<<<1024, 256>>>(t3, pT3h, 256 * 256 * 256);

    dim3 lin_grid(B_SZ / 64, K_SZ / 128);
    dim3 bil_grid(B_SZ / 128, K_SZ);  // x fast -> 32 CTAs share T[k] via L2

    // Phase 1: r1
    linear_f16<<<lin_grid, 256>>>(pSh, pVh, pW1h, b1, pL, 512);
    bilinear_f16<512, 512><<<bil_grid, 256>>>(pT1h, pS, pVh, pL, pR1, pR1h);

    // Phase 2: r2
    linear_f16<<<lin_grid, 256>>>(pVh, pOh, pW2h, b2, pL, 512);
    bilinear_f16<512, 512><<<bil_grid, 256>>>(pT2h, pV, pOh, pL, pR2, pR2h);

    // Phase 3: r3
    linear_f16<<<lin_grid, 256>>>(pR1h, pR2h, pW3h, b3, pL, 256);
    bilinear_f16<256, 256><<<bil_grid, 256>>>(pT3h, pR1, pR2h, pL, out, pR1h);
}